// round 15
// baseline (speedup 1.0000x reference)
#include <cuda_runtime.h>
#include <math.h>

// Problem constants
#define BATCH 8
#define CHAN  256
#define HH    512
#define WW    512
#define POOL  16
#define PH    (HH / POOL)          // 32
#define PW    (WW / POOL)          // 32
#define NPC   (BATCH * PH * PW)    // 8192 pooled elems per channel
#define BLKS_PER_CHAN 4
#define GRIDP (CHAN * BLKS_PER_CHAN)      // 1024 persistent blocks, single wave
#define SLABS_PER_BLK (BATCH * PH / BLKS_PER_CHAN)  // 64 slabs (= 2 batches)

// Per-channel moment accumulators: [c][5] = {S1, S2, S11, S22, S12}
// Zero-initialized at module load; finalize_kernel re-zeroes after consuming,
// so every graph replay (and the initial correctness call) starts from zeros.
__device__ float g_acc[CHAN * 5];

// Persistent kernel: 1024 blocks x 256 threads, single wave. Block handles
// ONE channel (c = blk>>2) and 64 contiguous slabs (2 full batches x 32 ph =
// two 1MiB contiguous streams per tensor). Pooling is done entirely in
// registers + warp shuffles (R5-proven layout): warp w owns pooled columns
// [4w,4w+4); lane l: rowpar=l>>4, colg=(w<<4)|(l&15). Each pooled 16x16 cell
// is covered by 8 lanes of one warp; shfl_xor over {16,2,1} completes the
// cell sum in all 8 lanes. Every lane then accumulates the 5 moment terms
// into persistent registers (each cell counted 8x -> divide by 8 at the end).
// NO smem / NO barrier / NO atomics in the hot path. One barrier + 5 global
// atomics per BLOCK at the end (5120 atomics total, 20 per address).
//
// Tuning record (do not revisit):
//   Noise band is ~±8us run-to-run (identical R12 source: 567.7 then 575.9).
//   SLABS=1 epilogue/block -> 574.8, SLABS=2 -> 567.7, SLABS=4 -> 580.5.
//   Per-warp global atomics in hot path -> +300us. CTA-counter fusion -> +8us.
__global__ void __launch_bounds__(256, 8)
pool_stats_kernel(const float* __restrict__ f1, const float* __restrict__ f2) {
    const int blk = blockIdx.x;
    const int c   = blk >> 2;               // channel
    const int sub = blk & (BLKS_PER_CHAN - 1);
    const int b0  = sub * 2;                // first of 2 batches owned

    const int t = threadIdx.x;
    const int w = t >> 5;
    const int l = t & 31;
    const int rowpar = l >> 4;              // 0 or 1
    const int colg   = (w << 4) | (l & 15); // float4 column group 0..127

    float m0 = 0.0f, m1v = 0.0f, m2 = 0.0f, m3 = 0.0f, m4 = 0.0f;

    for (int s = 0; s < SLABS_PER_BLK; s++) {
        const int bl = s >> 5;              // 0..1 batch within this block
        const int ph = s & (PH - 1);        // 0..31
        const size_t base =
            (((size_t)((b0 + bl) * CHAN + c)) * HH + (size_t)ph * POOL) * WW;
        const float4* __restrict__ p1 = (const float4*)(f1 + base);
        const float4* __restrict__ p2 = (const float4*)(f2 + base);

        float a1 = 0.0f, a2 = 0.0f;
#pragma unroll
        for (int it = 0; it < 8; it++) {
            const int row = rowpar + 2 * it;
            const float4 v1 = __ldcs(&p1[row * (WW / 4) + colg]);  // streaming
            const float4 v2 = __ldcs(&p2[row * (WW / 4) + colg]);
            a1 += (v1.x + v1.y) + (v1.z + v1.w);
            a2 += (v2.x + v2.y) + (v2.z + v2.w);
        }

        // Complete each pooled cell's 256-elem sum across its 8 lanes.
        a1 += __shfl_xor_sync(0xffffffffu, a1, 16);
        a2 += __shfl_xor_sync(0xffffffffu, a2, 16);
        a1 += __shfl_xor_sync(0xffffffffu, a1, 2);
        a2 += __shfl_xor_sync(0xffffffffu, a2, 2);
        a1 += __shfl_xor_sync(0xffffffffu, a1, 1);
        a2 += __shfl_xor_sync(0xffffffffu, a2, 1);

        const float pv1 = a1 * (1.0f / 256.0f);   // pooled value f1
        const float pv2 = a2 * (1.0f / 256.0f);   // pooled value f2

        // Every lane accumulates (8x duplication folded out at the end).
        m0  += pv1;
        m1v += pv2;
        m2  += pv1 * pv1;
        m3  += pv2 * pv2;
        m4  += pv1 * pv2;
    }

    // ---- once-per-block epilogue ----
    // Warp reduction (each cell counted 8x across lanes).
#pragma unroll
    for (int off = 16; off > 0; off >>= 1) {
        m0  += __shfl_xor_sync(0xffffffffu, m0,  off);
        m1v += __shfl_xor_sync(0xffffffffu, m1v, off);
        m2  += __shfl_xor_sync(0xffffffffu, m2,  off);
        m3  += __shfl_xor_sync(0xffffffffu, m3,  off);
        m4  += __shfl_xor_sync(0xffffffffu, m4,  off);
    }

    __shared__ float wm[8][5];
    if (l == 0) {
        wm[w][0] = m0; wm[w][1] = m1v; wm[w][2] = m2; wm[w][3] = m3; wm[w][4] = m4;
    }
    __syncthreads();

    if (t < 5) {   // one thread per moment -> 5 parallel atomics per block
        float v = 0.0f;
#pragma unroll
        for (int q = 0; q < 8; q++) v += wm[q][t];
        atomicAdd(&g_acc[c * 5 + t], v * 0.125f);   // undo 8x lane duplication
    }
    // Moment contributions published; allow the dependent finalize grid in.
    cudaTriggerProgrammaticLaunchCompletion();
}

__global__ void finalize_kernel(float* __restrict__ out) {
    const int c = threadIdx.x;  // 256 threads, one per channel

    // Wait for all pool_stats blocks (PDL); their atomics are then visible.
    cudaGridDependencySynchronize();

    const float n = (float)NPC;

    const float s1v = g_acc[c * 5 + 0];
    const float s2v = g_acc[c * 5 + 1];
    const float s11 = g_acc[c * 5 + 2];
    const float s22 = g_acc[c * 5 + 3];
    const float s12 = g_acc[c * 5 + 4];

    const float mA = s1v / n;
    const float mB = s2v / n;
    const float cov = s12 / n - mA * mB;                 // biased covariance
    const float ssd1 = s11 - s1v * s1v / n;              // sum squared deviations
    const float ssd2 = s22 - s2v * s2v / n;
    const float std1 = sqrtf(fmaxf(ssd1, 0.0f) / (n - 1.0f));  // unbiased std
    const float std2 = sqrtf(fmaxf(ssd2, 0.0f) / (n - 1.0f));
    const float corr = cov / (std1 * std2 + 1e-8f);
    const float a = fabsf(corr);

    __shared__ float red[CHAN];
    red[c] = a;
    __syncthreads();
#pragma unroll
    for (int s = CHAN / 2; s > 0; s >>= 1) {
        if (c < s) red[c] += red[c + s];
        __syncthreads();
    }
    if (c == 0) out[0] = 1.0f - red[0] / (float)CHAN;

    // Re-zero the accumulators for the next graph replay.
#pragma unroll
    for (int q = 0; q < 5; q++) g_acc[c * 5 + q] = 0.0f;
}

extern "C" void kernel_launch(void* const* d_in, const int* in_sizes, int n_in,
                              void* d_out, int out_size) {
    const float* f1 = (const float*)d_in[0];
    const float* f2 = (const float*)d_in[1];
    float* out = (float*)d_out;

    pool_stats_kernel<<<GRIDP, 256>>>(f1, f2);

    // Finalize with programmatic dependent launch: its launch latency and
    // prologue overlap the main kernel's tail.
    cudaLaunchConfig_t cfg = {};
    cfg.gridDim = dim3(1, 1, 1);
    cfg.blockDim = dim3(CHAN, 1, 1);
    cfg.dynamicSmemBytes = 0;
    cfg.stream = 0;
    cudaLaunchAttribute attrs[1];
    attrs[0].id = cudaLaunchAttributeProgrammaticStreamSerialization;
    attrs[0].val.programmaticStreamSerializationAllowed = 1;
    cfg.attrs = attrs;
    cfg.numAttrs = 1;
    cudaLaunchKernelEx(&cfg, finalize_kernel, out);
}

// round 16
// speedup vs baseline: 1.0115x; 1.0115x over previous
#include <cuda_runtime.h>
#include <math.h>

// Problem constants
#define BATCH 8
#define CHAN  256
#define HH    512
#define WW    512
#define POOL  16
#define PH    (HH / POOL)          // 32
#define PW    (WW / POOL)          // 32
#define NPC   (BATCH * PH * PW)    // 8192 pooled elems per channel
#define GRID2 (BATCH * CHAN * PH / 2)  // 32768 blocks, 2 ph-slabs each

// Per-channel moment accumulators: [c][5] = {S1, S2, S11, S22, S12}
// Zero-initialized at module load; finalize_kernel re-zeroes after consuming,
// so every graph replay (and the initial correctness call) starts from zeros.
__device__ float g_acc[CHAN * 5];

// One block per (b, c, ph-pair): two adjacent 16-row slabs = 64 KiB/tensor,
// contiguous. 256 threads. Thread t: rowpar = t>>7 (0/1), colg = t&127
// (float4 group along W) -- one 512B coalesced segment per warp-instruction.
// Each slab's per-thread partials go to smem; ONE barrier after both slabs;
// warp 0 reduces both slabs' pooled values into the 5 moments and issues
// exactly 5 global atomics per block.
//
// FINAL tuning record (settled; do not revisit):
//   Run-to-run noise band ~±8us (identical source: 567.7 / 575.9).
//   Slab granularity: 1 -> 574.8, 2 -> 567.7 (OPTIMUM), 4 -> 580.5.
//   Persistent single-wave (1024 blocks) -> 582.1 (exposed to per-SM max
//     instead of wave-averaging; spr floor 1.10 applies directly).
//   Per-warp global atomics (40/block) -> 874 (+300us L2 atomic serialization).
//   In-kernel CTA-counter fusion of finalize -> +8us vs PDL.
//   __ldcs streaming loads: ~neutral-positive, kept.
//   PDL finalize: hides the ~5us serial finalize launch, kept.
__global__ void __launch_bounds__(256, 8)
pool_stats_kernel(const float* __restrict__ f1, const float* __restrict__ f2) {
    const int blk = blockIdx.x;
    const int phpair = blk & (PH / 2 - 1);   // 0..15, fastest: contiguous memory
    const int c  = (blk >> 4) & (CHAN - 1);
    const int b  = blk >> 12;

    const int t = threadIdx.x;
    const int rowpar = t >> 7;     // 0 or 1
    const int colg   = t & 127;    // float4 column group 0..127

    const size_t base0 =
        (((size_t)(b * CHAN + c)) * HH + (size_t)phpair * (2 * POOL)) * WW;

    __shared__ float s1a[256], s2a[256];   // slab 0 partials
    __shared__ float s1b[256], s2b[256];   // slab 1 partials

    // ---- slab 0 ----
    {
        const float4* __restrict__ p1 = (const float4*)(f1 + base0);
        const float4* __restrict__ p2 = (const float4*)(f2 + base0);
        float a1 = 0.0f, a2 = 0.0f;
#pragma unroll
        for (int it = 0; it < 8; it++) {
            const int row = rowpar + 2 * it;
            const float4 v1 = __ldcs(&p1[row * (WW / 4) + colg]);
            const float4 v2 = __ldcs(&p2[row * (WW / 4) + colg]);
            a1 += (v1.x + v1.y) + (v1.z + v1.w);
            a2 += (v2.x + v2.y) + (v2.z + v2.w);
        }
        s1a[t] = a1;
        s2a[t] = a2;
    }

    // ---- slab 1 (next 16 rows; contiguous 32 KiB further) ----
    {
        const float4* __restrict__ p1 = (const float4*)(f1 + base0 + (size_t)POOL * WW);
        const float4* __restrict__ p2 = (const float4*)(f2 + base0 + (size_t)POOL * WW);
        float a1 = 0.0f, a2 = 0.0f;
#pragma unroll
        for (int it = 0; it < 8; it++) {
            const int row = rowpar + 2 * it;
            const float4 v1 = __ldcs(&p1[row * (WW / 4) + colg]);
            const float4 v2 = __ldcs(&p2[row * (WW / 4) + colg]);
            a1 += (v1.x + v1.y) + (v1.z + v1.w);
            a2 += (v2.x + v2.y) + (v2.z + v2.w);
        }
        s1b[t] = a1;
        s2b[t] = a2;
    }

    __syncthreads();

    if (t < PW) {  // 32 threads, one per pooled column (warp 0)
        float m0 = 0.0f, m1v = 0.0f, m2 = 0.0f, m3 = 0.0f, m4 = 0.0f;

        // slab 0 pooled value for column t
        {
            float q1 = 0.0f, q2 = 0.0f;
#pragma unroll
            for (int q = 0; q < 4; q++) {
                q1 += s1a[4 * t + q] + s1a[128 + 4 * t + q];
                q2 += s2a[4 * t + q] + s2a[128 + 4 * t + q];
            }
            const float pv1 = q1 * (1.0f / 256.0f);
            const float pv2 = q2 * (1.0f / 256.0f);
            m0 += pv1; m1v += pv2;
            m2 += pv1 * pv1; m3 += pv2 * pv2; m4 += pv1 * pv2;
        }
        // slab 1 pooled value for column t
        {
            float q1 = 0.0f, q2 = 0.0f;
#pragma unroll
            for (int q = 0; q < 4; q++) {
                q1 += s1b[4 * t + q] + s1b[128 + 4 * t + q];
                q2 += s2b[4 * t + q] + s2b[128 + 4 * t + q];
            }
            const float pv1 = q1 * (1.0f / 256.0f);
            const float pv2 = q2 * (1.0f / 256.0f);
            m0 += pv1; m1v += pv2;
            m2 += pv1 * pv1; m3 += pv2 * pv2; m4 += pv1 * pv2;
        }

#pragma unroll
        for (int off = 16; off > 0; off >>= 1) {
            m0  += __shfl_down_sync(0xffffffffu, m0,  off);
            m1v += __shfl_down_sync(0xffffffffu, m1v, off);
            m2  += __shfl_down_sync(0xffffffffu, m2,  off);
            m3  += __shfl_down_sync(0xffffffffu, m3,  off);
            m4  += __shfl_down_sync(0xffffffffu, m4,  off);
        }
        if (t == 0) {
            atomicAdd(&g_acc[c * 5 + 0], m0);
            atomicAdd(&g_acc[c * 5 + 1], m1v);
            atomicAdd(&g_acc[c * 5 + 2], m2);
            atomicAdd(&g_acc[c * 5 + 3], m3);
            atomicAdd(&g_acc[c * 5 + 4], m4);
        }
    }
    // All moment contributions are published; allow the dependent finalize
    // grid to launch while remaining blocks drain.
    cudaTriggerProgrammaticLaunchCompletion();
}

__global__ void finalize_kernel(float* __restrict__ out) {
    const int c = threadIdx.x;  // 256 threads, one per channel

    // Wait for all pool_stats blocks (PDL); their atomics are then visible.
    cudaGridDependencySynchronize();

    const float n = (float)NPC;

    const float s1v = g_acc[c * 5 + 0];
    const float s2v = g_acc[c * 5 + 1];
    const float s11 = g_acc[c * 5 + 2];
    const float s22 = g_acc[c * 5 + 3];
    const float s12 = g_acc[c * 5 + 4];

    const float mA = s1v / n;
    const float mB = s2v / n;
    const float cov = s12 / n - mA * mB;                 // biased covariance
    const float ssd1 = s11 - s1v * s1v / n;              // sum squared deviations
    const float ssd2 = s22 - s2v * s2v / n;
    const float std1 = sqrtf(fmaxf(ssd1, 0.0f) / (n - 1.0f));  // unbiased std
    const float std2 = sqrtf(fmaxf(ssd2, 0.0f) / (n - 1.0f));
    const float corr = cov / (std1 * std2 + 1e-8f);
    const float a = fabsf(corr);

    __shared__ float red[CHAN];
    red[c] = a;
    __syncthreads();
#pragma unroll
    for (int s = CHAN / 2; s > 0; s >>= 1) {
        if (c < s) red[c] += red[c + s];
        __syncthreads();
    }
    if (c == 0) out[0] = 1.0f - red[0] / (float)CHAN;

    // Re-zero the accumulators for the next graph replay.
#pragma unroll
    for (int q = 0; q < 5; q++) g_acc[c * 5 + q] = 0.0f;
}

extern "C" void kernel_launch(void* const* d_in, const int* in_sizes, int n_in,
                              void* d_out, int out_size) {
    const float* f1 = (const float*)d_in[0];
    const float* f2 = (const float*)d_in[1];
    float* out = (float*)d_out;

    pool_stats_kernel<<<GRID2, 256>>>(f1, f2);

    // Finalize with programmatic dependent launch: its launch latency and
    // prologue overlap the main kernel's tail waves.
    cudaLaunchConfig_t cfg = {};
    cfg.gridDim = dim3(1, 1, 1);
    cfg.blockDim = dim3(CHAN, 1, 1);
    cfg.dynamicSmemBytes = 0;
    cfg.stream = 0;
    cudaLaunchAttribute attrs[1];
    attrs[0].id = cudaLaunchAttributeProgrammaticStreamSerialization;
    attrs[0].val.programmaticStreamSerializationAllowed = 1;
    cfg.attrs = attrs;
    cfg.numAttrs = 1;
    cudaLaunchKernelEx(&cfg, finalize_kernel, out);
}